// round 15
// baseline (speedup 1.0000x reference)
#include <cuda_runtime.h>
#include <cuda_fp16.h>
#include <cstdint>

#define DMODEL 512
#define NHEAD  8
#define DK     64
#define BATCH  2
#define SEQ    4096
#define MTOT   (BATCH*SEQ)   // 8192

// Scratch (static device arrays — no runtime allocation). All fp16.
__device__ __half g_qh[(size_t)BATCH*NHEAD*SEQ*DK];   // [B,H,S,Dk], *(log2e/8)
__device__ __half g_kh[(size_t)BATCH*NHEAD*SEQ*DK];   // [B,H,S,Dk]
__device__ __half g_vh[(size_t)BATCH*NHEAD*SEQ*DK];   // [B,H,Dk,S] TRANSPOSED
__device__ __half g_att[(size_t)MTOT*DMODEL];         // [B,S,D]
__device__ __half g_rq[(size_t)MTOT*DMODEL];          // fp16 inputs
__device__ __half g_rk[(size_t)MTOT*DMODEL];
__device__ __half g_rv[(size_t)MTOT*DMODEL];
__device__ __half g_rw[(size_t)4*DMODEL*DMODEL];      // fp16 weights

// ---------------------------------------------------------------------------
__device__ __forceinline__ float ex2(float x) {
    float r;
    asm("ex2.approx.ftz.f32 %0, %1;" : "=f"(r) : "f"(x));
    return r;
}

__device__ __forceinline__ void mma_f16(float* d, const uint32_t* a,
                                        uint32_t b0, uint32_t b1) {
    asm volatile(
        "mma.sync.aligned.m16n8k16.row.col.f32.f16.f16.f32 "
        "{%0,%1,%2,%3}, {%4,%5,%6,%7}, {%8,%9}, {%0,%1,%2,%3};\n"
        : "+f"(d[0]), "+f"(d[1]), "+f"(d[2]), "+f"(d[3])
        : "r"(a[0]), "r"(a[1]), "r"(a[2]), "r"(a[3]), "r"(b0), "r"(b1));
}

__device__ __forceinline__ void ldsm4(uint32_t& r0, uint32_t& r1,
                                      uint32_t& r2, uint32_t& r3,
                                      uint32_t saddr) {
    asm volatile(
        "ldmatrix.sync.aligned.m8n8.x4.shared.b16 {%0,%1,%2,%3}, [%4];"
        : "=r"(r0), "=r"(r1), "=r"(r2), "=r"(r3) : "r"(saddr));
}

__device__ __forceinline__ uint32_t h2(float lo, float hi) {
    __half2 v = __floats2half2_rn(lo, hi);
    return *(uint32_t*)&v;
}

__device__ __forceinline__ void cp16(uint32_t saddr, const void* g) {
    asm volatile("cp.async.cg.shared.global [%0], [%1], 16;\n"
                 :: "r"(saddr), "l"(g));
}
__device__ __forceinline__ void cpcommit() {
    asm volatile("cp.async.commit_group;\n");
}
template<int N> __device__ __forceinline__ void cpwait() {
    asm volatile("cp.async.wait_group %0;\n" :: "n"(N));
}

// ---------------------------------------------------------------------------
// Merged f32 -> f16 conversion: blockIdx.y 0..2 = q,k,v inputs (n4x items),
// 3..6 = weights wq..wo into g_rw (n4w items). Strided loop handles sizes.
// ---------------------------------------------------------------------------
__global__ void conv_all(const float4* __restrict__ q,
                         const float4* __restrict__ k,
                         const float4* __restrict__ v,
                         const float4* __restrict__ wq,
                         const float4* __restrict__ wk,
                         const float4* __restrict__ wv,
                         const float4* __restrict__ wo,
                         __half2* __restrict__ rq, __half2* __restrict__ rk,
                         __half2* __restrict__ rv, __half2* __restrict__ rw,
                         int n4x, int n4w)
{
    const int y = blockIdx.y;
    const float4* s;
    __half2* d;
    int n4;
    if (y < 3) {
        s = (y == 0) ? q : (y == 1) ? k : v;
        d = (y == 0) ? rq : (y == 1) ? rk : rv;
        n4 = n4x;
    } else {
        const int w = y - 3;
        s = (w == 0) ? wq : (w == 1) ? wk : (w == 2) ? wv : wo;
        d = rw + (size_t)w * n4w * 2;
        n4 = n4w;
    }
    for (int i = blockIdx.x * blockDim.x + threadIdx.x; i < n4;
         i += gridDim.x * blockDim.x) {
        float4 t = s[i];
        d[i * 2 + 0] = __floats2half2_rn(t.x, t.y);
        d[i * 2 + 1] = __floats2half2_rn(t.z, t.w);
    }
}

// ---------------------------------------------------------------------------
// fp16 GEMM core, k128 stages (R15): 128x128 tile, K=512 in 4 stages of 128,
// double-buffered cp.async, ldmatrix.x4. Halves barrier crossings (8 vs 16)
// and doubles MMA work per sync (64/warp) to cover latency.
// Pitch 136 halves: row stride 272B -> ldsm rows hit distinct 16B banks.
// ---------------------------------------------------------------------------
#define GP2 136
#define GST2 (128*GP2)                 // halves per operand per stage
#define GEMM_SMEM (4*GST2*2)           // 139264 B (1 CTA/SM)

template<int LAYOUT>
__device__ __forceinline__
void gemm_body(const __half* __restrict__ X, const __half* __restrict__ W,
               const float* __restrict__ bias, void* __restrict__ Yv,
               float scale, int m0, int n0, __half* smh)
{
    const int tid = threadIdx.x, lane = tid & 31, warp = tid >> 5;
    const int g = lane >> 2, tg = lane & 3;
    const int wm = (warp & 3) * 32, wn = (warp >> 2) * 64;
    const uint32_t sA = (uint32_t)__cvta_generic_to_shared(smh);
    const uint32_t sB = sA + 2 * GST2 * 2;
    const int lj  = lane >> 3, lr = lane & 7;
    const int rA8 = (lj & 1) * 8, kA8 = (lj >> 1) * 8;
    const int rB8 = (lj >> 1) * 8, kB8 = (lj & 1) * 8;

    // stage fill: A = 2048 chunks (128 rows x 16 chunks of 8 halves), B same.
#define G_ISSUE(st, k0)                                                        \
    {                                                                          \
        _Pragma("unroll")                                                      \
        for (int i = 0; i < 16; i++) {                                         \
            int c = tid + i * 256;                                             \
            int r = (c >> 4) & 127, ch = c & 15;                               \
            if (c < 2048)                                                      \
                cp16(sA + (st) * GST2 * 2 + r * (GP2 * 2) + ch * 16,           \
                     X + (size_t)(m0 + r) * DMODEL + (k0) + ch * 8);           \
            else                                                               \
                cp16(sB + (st) * GST2 * 2 + r * (GP2 * 2) + ch * 16,           \
                     W + (size_t)(n0 + r) * DMODEL + (k0) + ch * 8);           \
        }                                                                      \
    }

    G_ISSUE(0, 0);   cpcommit();
    G_ISSUE(1, 128); cpcommit();

    float acc[2][8][4];
#pragma unroll
    for (int t = 0; t < 2; t++)
#pragma unroll
        for (int j = 0; j < 8; j++)
#pragma unroll
            for (int c = 0; c < 4; c++) acc[t][j][c] = 0.f;

    for (int kt = 0; kt < 4; kt++) {
        cpwait<1>();
        __syncthreads();
        const uint32_t Ab = sA + (kt & 1) * GST2 * 2;
        const uint32_t Bb = sB + (kt & 1) * GST2 * 2;
#pragma unroll
        for (int kc = 0; kc < 8; kc++) {
            uint32_t a[2][4];
#pragma unroll
            for (int t = 0; t < 2; t++) {
                const int row = wm + t * 16 + rA8 + lr;
                const int ko  = kc * 16 + kA8;
                ldsm4(a[t][0], a[t][1], a[t][2], a[t][3],
                      Ab + (row * GP2 + ko) * 2);
            }
#pragma unroll
            for (int jp = 0; jp < 4; jp++) {
                uint32_t b[4];
                const int row = wn + jp * 16 + rB8 + lr;
                const int ko  = kc * 16 + kB8;
                ldsm4(b[0], b[1], b[2], b[3], Bb + (row * GP2 + ko) * 2);
                mma_f16(acc[0][2 * jp    ], a[0], b[0], b[1]);
                mma_f16(acc[1][2 * jp    ], a[1], b[0], b[1]);
                mma_f16(acc[0][2 * jp + 1], a[0], b[2], b[3]);
                mma_f16(acc[1][2 * jp + 1], a[1], b[2], b[3]);
            }
        }
        __syncthreads();
        if (kt + 2 < 4) { G_ISSUE(kt & 1, (kt + 2) * 128); }
        cpcommit();
    }

#pragma unroll
    for (int t = 0; t < 2; t++) {
#pragma unroll
        for (int rr = 0; rr < 2; rr++) {
            const int r = m0 + wm + t * 16 + g + rr * 8;
            const int bb = r >> 12, ss = r & 4095;
#pragma unroll
            for (int j = 0; j < 8; j++) {
                const int n = n0 + wn + j * 8 + 2 * tg;
                float2 bi = *(const float2*)&bias[n];
                float v0 = (acc[t][j][rr * 2 + 0] + bi.x) * scale;
                float v1 = (acc[t][j][rr * 2 + 1] + bi.y) * scale;
                if (LAYOUT == 0) {
                    *(float2*)&((float*)Yv)[(size_t)r * DMODEL + n]
                        = make_float2(v0, v1);
                } else if (LAYOUT == 1) {
                    const int h = n >> 6, d = n & 63;
                    *(__half2*)&((__half*)Yv)[
                        (((size_t)(bb * NHEAD + h)) * SEQ + ss) * DK + d]
                        = __floats2half2_rn(v0, v1);
                } else {
                    const int h = n >> 6, d = n & 63;
                    __half* yb = (__half*)Yv
                        + (((size_t)(bb * NHEAD + h)) * DK + d) * SEQ + ss;
                    yb[0]   = __float2half_rn(v0);
                    yb[SEQ] = __float2half_rn(v1);
                }
            }
        }
    }
#undef G_ISSUE
}

// Fused QKV projections: blockIdx.z selects input/weight/output.
__global__ __launch_bounds__(256)
void gemm_qkv(const __half* __restrict__ rq, const __half* __restrict__ rk,
              const __half* __restrict__ rv, const __half* __restrict__ rw,
              const float* __restrict__ bq, const float* __restrict__ bk,
              const float* __restrict__ bv,
              __half* __restrict__ qh, __half* __restrict__ kh,
              __half* __restrict__ vh, float qscale)
{
    extern __shared__ __half smh[];
    const int m0 = blockIdx.y * 128, n0 = blockIdx.x * 128;
    const int DD = DMODEL * DMODEL;
    if (blockIdx.z == 0)
        gemm_body<1>(rq, rw,          bq, qh, qscale, m0, n0, smh);
    else if (blockIdx.z == 1)
        gemm_body<1>(rk, rw + DD,     bk, kh, 1.0f,   m0, n0, smh);
    else
        gemm_body<2>(rv, rw + 2 * DD, bv, vh, 1.0f,   m0, n0, smh);
}

// Output projection (fp32 result into d_out)
__global__ __launch_bounds__(256)
void gemm_o(const __half* __restrict__ X, const __half* __restrict__ W,
            const float* __restrict__ bias, float* __restrict__ Y)
{
    extern __shared__ __half smh[];
    gemm_body<0>(X, W, bias, Y, 1.0f, blockIdx.y * 128, blockIdx.x * 128, smh);
}

// ---------------------------------------------------------------------------
// fp16 flash attention (EXACT R9/R14 best: 221us, at the mma.sync rate wall):
// 256 thr (8 warps) x 256 query rows, 32 rows/warp (2 m16 halves, K/V
// fragments shared). P entirely in registers. ldmatrix.x4 fragments.
// Softmax in exp2 domain (log2e folded into Q projection scale).
// ---------------------------------------------------------------------------
#define HP 72
#define QROWS 256
#define KVB (64*HP)                       // halves per K or V stage
#define SM_K (QROWS*HP)                   // Q buffer first
#define SM_V (SM_K + 2*KVB)
#define ATT_SMEM ((SM_V + 2*KVB)*2)       // 73728 B

__global__ __launch_bounds__(256)
void attn_kernel()
{
    extern __shared__ __half smh[];

    const int bh = blockIdx.y, q0 = blockIdx.x * QROWS;
    const int tid = threadIdx.x, lane = tid & 31, warp = tid >> 5;
    const int w32 = warp * 32;
    const int lj = lane >> 3, lr = lane & 7;
    const int rA8 = (lj & 1) * 8, kA8 = (lj >> 1) * 8;
    const int rB8 = (lj >> 1) * 8, kB8 = (lj & 1) * 8;

    const __half* Qg = g_qh + (size_t)bh * SEQ * DK + (size_t)q0 * DK;
    const __half* Kg = g_kh + (size_t)bh * SEQ * DK;
    const __half* Vg = g_vh + (size_t)bh * DK * SEQ;

    const uint32_t sQ = (uint32_t)__cvta_generic_to_shared(smh);
    const uint32_t sK = sQ + SM_K * 2;
    const uint32_t sV = sQ + SM_V * 2;

    // Q tile: 256 rows x 8 chunks = 2048
#pragma unroll
    for (int i = 0; i < 8; i++) {
        int c = tid + i * 256;
        int row = c >> 3, ch = c & 7;
        cp16(sQ + row * (HP * 2) + ch * 16, Qg + (size_t)row * DK + ch * 8);
    }
    cpcommit();

#define KV_ISSUE(st, ktile)                                                    \
    {                                                                          \
        _Pragma("unroll")                                                      \
        for (int i = 0; i < 4; i++) {                                          \
            int c = tid + i * 256;                                             \
            int r = (c >> 3) & 63, ch = c & 7;                                 \
            if (c < 512)                                                       \
                cp16(sK + (st) * (KVB * 2) + r * (HP * 2) + ch * 16,           \
                     Kg + ((size_t)(ktile) * 64 + r) * DK + ch * 8);           \
            else                                                               \
                cp16(sV + (st) * (KVB * 2) + r * (HP * 2) + ch * 16,           \
                     Vg + (size_t)r * SEQ + (ktile) * 64 + ch * 8);            \
        }                                                                      \
    }

    KV_ISSUE(0, 0); cpcommit();
    KV_ISSUE(1, 1); cpcommit();

    cpwait<2>();
    __syncthreads();

    // Q fragments via ldmatrix: 2 halves x 4 k16 chunks
    uint32_t qa[2][4][4];
#pragma unroll
    for (int h = 0; h < 2; h++)
#pragma unroll
        for (int kc = 0; kc < 4; kc++) {
            const int row = w32 + h * 16 + rA8 + lr;
            const int ko  = kc * 16 + kA8;
            ldsm4(qa[h][kc][0], qa[h][kc][1], qa[h][kc][2], qa[h][kc][3],
                  sQ + (row * HP + ko) * 2);
        }

    float o[2][8][4];
    float m[2][2], l[2][2];
#pragma unroll
    for (int h = 0; h < 2; h++) {
        m[h][0] = -1e30f; m[h][1] = -1e30f; l[h][0] = 0.f; l[h][1] = 0.f;
#pragma unroll
        for (int nt = 0; nt < 8; nt++)
#pragma unroll
            for (int c = 0; c < 4; c++) o[h][nt][c] = 0.f;
    }

    for (int kt = 0; kt < SEQ / 64; kt++) {
        cpwait<1>();
        __syncthreads();
        const uint32_t kbase = sK + (kt & 1) * (KVB * 2);
        const uint32_t vbase = sV + (kt & 1) * (KVB * 2);

        // ---- S = Q @ K^T ----
        float sc[2][8][4];
#pragma unroll
        for (int h = 0; h < 2; h++)
#pragma unroll
            for (int nt = 0; nt < 8; nt++)
#pragma unroll
                for (int c = 0; c < 4; c++) sc[h][nt][c] = 0.f;

#pragma unroll
        for (int kc = 0; kc < 4; kc++) {
            uint32_t kb[4][4];
#pragma unroll
            for (int np = 0; np < 4; np++) {
                const int key = np * 16 + rB8 + lr;
                const int ko  = kc * 16 + kB8;
                ldsm4(kb[np][0], kb[np][1], kb[np][2], kb[np][3],
                      kbase + (key * HP + ko) * 2);
            }
#pragma unroll
            for (int np = 0; np < 4; np++) {
                mma_f16(sc[0][2 * np    ], qa[0][kc], kb[np][0], kb[np][1]);
                mma_f16(sc[1][2 * np    ], qa[1][kc], kb[np][0], kb[np][1]);
                mma_f16(sc[0][2 * np + 1], qa[0][kc], kb[np][2], kb[np][3]);
                mma_f16(sc[1][2 * np + 1], qa[1][kc], kb[np][2], kb[np][3]);
            }
        }

        // ---- Online softmax (exp2 domain); p overwrites sc ----
#pragma unroll
        for (int h = 0; h < 2; h++) {
            float mx0 = -1e30f, mx1 = -1e30f;
#pragma unroll
            for (int nt = 0; nt < 8; nt++) {
                mx0 = fmaxf(mx0, fmaxf(sc[h][nt][0], sc[h][nt][1]));
                mx1 = fmaxf(mx1, fmaxf(sc[h][nt][2], sc[h][nt][3]));
            }
            mx0 = fmaxf(mx0, __shfl_xor_sync(0xffffffffu, mx0, 1));
            mx0 = fmaxf(mx0, __shfl_xor_sync(0xffffffffu, mx0, 2));
            mx1 = fmaxf(mx1, __shfl_xor_sync(0xffffffffu, mx1, 1));
            mx1 = fmaxf(mx1, __shfl_xor_sync(0xffffffffu, mx1, 2));

            const float mn0 = fmaxf(m[h][0], mx0), mn1 = fmaxf(m[h][1], mx1);
            const float c0 = ex2(m[h][0] - mn0), c1 = ex2(m[h][1] - mn1);
            m[h][0] = mn0; m[h][1] = mn1;

            float s0 = 0.f, s1 = 0.f;
#pragma unroll
            for (int nt = 0; nt < 8; nt++) {
                sc[h][nt][0] = ex2(sc[h][nt][0] - mn0);
                sc[h][nt][1] = ex2(sc[h][nt][1] - mn0);
                sc[h][nt][2] = ex2(sc[h][nt][2] - mn1);
                sc[h][nt][3] = ex2(sc[h][nt][3] - mn1);
                s0 += sc[h][nt][0] + sc[h][nt][1];
                s1 += sc[h][nt][2] + sc[h][nt][3];
            }
            s0 += __shfl_xor_sync(0xffffffffu, s0, 1);
            s0 += __shfl_xor_sync(0xffffffffu, s0, 2);
            s1 += __shfl_xor_sync(0xffffffffu, s1, 1);
            s1 += __shfl_xor_sync(0xffffffffu, s1, 2);
            l[h][0] = l[h][0] * c0 + s0;
            l[h][1] = l[h][1] * c1 + s1;
#pragma unroll
            for (int nt = 0; nt < 8; nt++) {
                o[h][nt][0] *= c0; o[h][nt][1] *= c0;
                o[h][nt][2] *= c1; o[h][nt][3] *= c1;
            }
        }

        // ---- O += P @ V : P packed in registers (C-frag == A-frag) ----
#pragma unroll
        for (int kc = 0; kc < 4; kc++) {
            uint32_t vb[4][4];
#pragma unroll
            for (int np = 0; np < 4; np++) {
                const int d  = np * 16 + rB8 + lr;
                const int ko = kc * 16 + kB8;
                ldsm4(vb[np][0], vb[np][1], vb[np][2], vb[np][3],
                      vbase + (d * HP + ko) * 2);
            }
            const int n0b = 2 * kc, n1b = 2 * kc + 1;
            uint32_t pa0[4], pa1[4];
            pa0[0] = h2(sc[0][n0b][0], sc[0][n0b][1]);
            pa0[1] = h2(sc[0][n0b][2], sc[0][n0b][3]);
            pa0[2] = h2(sc[0][n1b][0], sc[0][n1b][1]);
            pa0[3] = h2(sc[0][n1b][2], sc[0][n1b][3]);
            pa1[0] = h2(sc[1][n0b][0], sc[1][n0b][1]);
            pa1[1] = h2(sc[1][n0b][2], sc[1][n0b][3]);
            pa1[2] = h2(sc[1][n1b][0], sc[1][n1b][1]);
            pa1[3] = h2(sc[1][n1b][2], sc[1][n1b][3]);
#pragma unroll
            for (int np = 0; np < 4; np++) {
                mma_f16(o[0][2 * np    ], pa0, vb[np][0], vb[np][1]);
                mma_f16(o[1][2 * np    ], pa1, vb[np][0], vb[np][1]);
                mma_f16(o[0][2 * np + 1], pa0, vb[np][2], vb[np][3]);
                mma_f16(o[1][2 * np + 1], pa1, vb[np][2], vb[np][3]);
            }
        }
        __syncthreads();   // all warps done with stage before refill
        if (kt + 2 < SEQ / 64) { KV_ISSUE(kt & 1, kt + 2); }
        cpcommit();
    }

    // Epilogue: normalize, write fp16 [B,S,D] (feeds fp16 O-GEMM)
    const int g = lane >> 2, tg = lane & 3;
    const int bb = bh >> 3, hh = bh & 7;
    __half* Og = g_att + ((size_t)bb * SEQ + q0) * DMODEL + hh * DK;
#pragma unroll
    for (int h = 0; h < 2; h++) {
#pragma unroll
        for (int rr = 0; rr < 2; rr++) {
            const float inv = 1.0f / l[h][rr];
            const int row = w32 + h * 16 + g + rr * 8;
#pragma unroll
            for (int nt = 0; nt < 8; nt++) {
                *(__half2*)&Og[(size_t)row * DMODEL + nt * 8 + 2 * tg]
                    = __floats2half2_rn(o[h][nt][rr * 2 + 0] * inv,
                                        o[h][nt][rr * 2 + 1] * inv);
            }
        }
    }
#undef KV_ISSUE
}

// ---------------------------------------------------------------------------
extern "C" void kernel_launch(void* const* d_in, const int* in_sizes, int n_in,
                              void* d_out, int out_size)
{
    const float* q  = (const float*)d_in[0];
    const float* k  = (const float*)d_in[1];
    const float* v  = (const float*)d_in[2];
    const float* wq = (const float*)d_in[3];
    const float* bq = (const float*)d_in[4];
    const float* wk = (const float*)d_in[5];
    const float* bk = (const float*)d_in[6];
    const float* wv = (const float*)d_in[7];
    const float* bv = (const float*)d_in[8];
    const float* wo = (const float*)d_in[9];
    const float* bo = (const float*)d_in[10];

    __half *qh, *kh, *vh, *att, *rq, *rk, *rv, *rw;
    cudaGetSymbolAddress((void**)&qh,  g_qh);
    cudaGetSymbolAddress((void**)&kh,  g_kh);
    cudaGetSymbolAddress((void**)&vh,  g_vh);
    cudaGetSymbolAddress((void**)&att, g_att);
    cudaGetSymbolAddress((void**)&rq,  g_rq);
    cudaGetSymbolAddress((void**)&rk,  g_rk);
    cudaGetSymbolAddress((void**)&rv,  g_rv);
    cudaGetSymbolAddress((void**)&rw,  g_rw);

    cudaFuncSetAttribute(gemm_qkv,
        cudaFuncAttributeMaxDynamicSharedMemorySize, GEMM_SMEM);
    cudaFuncSetAttribute(gemm_o,
        cudaFuncAttributeMaxDynamicSharedMemorySize, GEMM_SMEM);
    cudaFuncSetAttribute(attn_kernel,
        cudaFuncAttributeMaxDynamicSharedMemorySize, ATT_SMEM);

    const int DD = DMODEL * DMODEL;
    const int n4x = MTOT * DMODEL / 4;   // 1048576
    const int n4w = DD / 4;              // 65536

    // L1: all conversions in one launch (y=0..2 inputs, y=3..6 weights)
    conv_all<<<dim3(256, 7), 256>>>((const float4*)q, (const float4*)k,
                                    (const float4*)v, (const float4*)wq,
                                    (const float4*)wk, (const float4*)wv,
                                    (const float4*)wo, (__half2*)rq,
                                    (__half2*)rk, (__half2*)rv,
                                    (__half2*)rw, n4x, n4w);

    const float QSCALE = 0.125f * 1.4426950408889634f;   // 1/sqrt(Dk) * log2e
    gemm_qkv<<<dim3(DMODEL / 128, MTOT / 128, 3), 256, GEMM_SMEM>>>(
        rq, rk, rv, rw, bq, bk, bv, qh, kh, vh, QSCALE);

    attn_kernel<<<dim3(SEQ / QROWS, BATCH * NHEAD), 256, ATT_SMEM>>>();

    gemm_o<<<dim3(DMODEL / 128, MTOT / 128), 256, GEMM_SMEM>>>(
        att, rw + 3 * DD, bo, (float*)d_out);
}

// round 16
// speedup vs baseline: 1.0262x; 1.0262x over previous
#include <cuda_runtime.h>
#include <cuda_fp16.h>
#include <cstdint>

#define DMODEL 512
#define NHEAD  8
#define DK     64
#define BATCH  2
#define SEQ    4096
#define MTOT   (BATCH*SEQ)   // 8192

// Scratch (static device arrays — no runtime allocation). All fp16.
__device__ __half g_qh[(size_t)BATCH*NHEAD*SEQ*DK];   // [B,H,S,Dk], *(log2e/8)
__device__ __half g_kh[(size_t)BATCH*NHEAD*SEQ*DK];   // [B,H,S,Dk]
__device__ __half g_vh[(size_t)BATCH*NHEAD*SEQ*DK];   // [B,H,Dk,S] TRANSPOSED
__device__ __half g_att[(size_t)MTOT*DMODEL];         // [B,S,D]
__device__ __half g_rq[(size_t)MTOT*DMODEL];          // fp16 inputs
__device__ __half g_rk[(size_t)MTOT*DMODEL];
__device__ __half g_rv[(size_t)MTOT*DMODEL];
__device__ __half g_rw[(size_t)4*DMODEL*DMODEL];      // fp16 weights

// ---------------------------------------------------------------------------
__device__ __forceinline__ float ex2(float x) {
    float r;
    asm("ex2.approx.ftz.f32 %0, %1;" : "=f"(r) : "f"(x));
    return r;
}

__device__ __forceinline__ void mma_f16(float* d, const uint32_t* a,
                                        uint32_t b0, uint32_t b1) {
    asm volatile(
        "mma.sync.aligned.m16n8k16.row.col.f32.f16.f16.f32 "
        "{%0,%1,%2,%3}, {%4,%5,%6,%7}, {%8,%9}, {%0,%1,%2,%3};\n"
        : "+f"(d[0]), "+f"(d[1]), "+f"(d[2]), "+f"(d[3])
        : "r"(a[0]), "r"(a[1]), "r"(a[2]), "r"(a[3]), "r"(b0), "r"(b1));
}

__device__ __forceinline__ void ldsm4(uint32_t& r0, uint32_t& r1,
                                      uint32_t& r2, uint32_t& r3,
                                      uint32_t saddr) {
    asm volatile(
        "ldmatrix.sync.aligned.m8n8.x4.shared.b16 {%0,%1,%2,%3}, [%4];"
        : "=r"(r0), "=r"(r1), "=r"(r2), "=r"(r3) : "r"(saddr));
}

__device__ __forceinline__ uint32_t h2(float lo, float hi) {
    __half2 v = __floats2half2_rn(lo, hi);
    return *(uint32_t*)&v;
}

__device__ __forceinline__ void cp16(uint32_t saddr, const void* g) {
    asm volatile("cp.async.cg.shared.global [%0], [%1], 16;\n"
                 :: "r"(saddr), "l"(g));
}
__device__ __forceinline__ void cpcommit() {
    asm volatile("cp.async.commit_group;\n");
}
template<int N> __device__ __forceinline__ void cpwait() {
    asm volatile("cp.async.wait_group %0;\n" :: "n"(N));
}

// ---------------------------------------------------------------------------
// Merged f32 -> f16 conversion: blockIdx.y 0..2 = q,k,v inputs (n4x items),
// 3..6 = weights wq..wo into g_rw (n4w items).
// ---------------------------------------------------------------------------
__global__ void conv_all(const float4* __restrict__ q,
                         const float4* __restrict__ k,
                         const float4* __restrict__ v,
                         const float4* __restrict__ wq,
                         const float4* __restrict__ wk,
                         const float4* __restrict__ wv,
                         const float4* __restrict__ wo,
                         __half2* __restrict__ rq, __half2* __restrict__ rk,
                         __half2* __restrict__ rv, __half2* __restrict__ rw,
                         int n4x, int n4w)
{
    const int y = blockIdx.y;
    const float4* s;
    __half2* d;
    int n4;
    if (y < 3) {
        s = (y == 0) ? q : (y == 1) ? k : v;
        d = (y == 0) ? rq : (y == 1) ? rk : rv;
        n4 = n4x;
    } else {
        const int w = y - 3;
        s = (w == 0) ? wq : (w == 1) ? wk : (w == 2) ? wv : wo;
        d = rw + (size_t)w * n4w * 2;
        n4 = n4w;
    }
    for (int i = blockIdx.x * blockDim.x + threadIdx.x; i < n4;
         i += gridDim.x * blockDim.x) {
        float4 t = s[i];
        d[i * 2 + 0] = __floats2half2_rn(t.x, t.y);
        d[i * 2 + 1] = __floats2half2_rn(t.z, t.w);
    }
}

// ---------------------------------------------------------------------------
// fp16 GEMM core, R16: k64 stages, THREE-stage cp.async ring (2 stages always
// in flight while one computes -> stage-wait exposure ~= load - 2*compute),
// pitch 72, ldmatrix.x4, 2 CTAs/SM (110.6KB x2 = 216KB smem).
// ---------------------------------------------------------------------------
#define HP 72
#define GST (128*HP)               // halves per stage per operand
#define GEMM_SMEM (6*GST*2)        // 110592 B (3 stages x A,B)

template<int LAYOUT>
__device__ __forceinline__
void gemm_body(const __half* __restrict__ X, const __half* __restrict__ W,
               const float* __restrict__ bias, void* __restrict__ Yv,
               float scale, int m0, int n0, __half* smh)
{
    const int tid = threadIdx.x, lane = tid & 31, warp = tid >> 5;
    const int g = lane >> 2, tg = lane & 3;
    const int wm = (warp & 3) * 32, wn = (warp >> 2) * 64;
    const uint32_t sA = (uint32_t)__cvta_generic_to_shared(smh);
    const uint32_t sB = sA + 3 * GST * 2;
    const int lj  = lane >> 3, lr = lane & 7;
    const int rA8 = (lj & 1) * 8, kA8 = (lj >> 1) * 8;
    const int rB8 = (lj >> 1) * 8, kB8 = (lj & 1) * 8;

#define G_ISSUE(st, k0)                                                        \
    {                                                                          \
        _Pragma("unroll")                                                      \
        for (int i = 0; i < 8; i++) {                                          \
            int c = tid + i * 256;                                             \
            int r = (c >> 3) & 127, ch = c & 7;                                \
            if (c < 1024)                                                      \
                cp16(sA + ((st) * GST + r * HP) * 2 + ch * 16,                 \
                     X + (size_t)(m0 + r) * DMODEL + (k0) + ch * 8);           \
            else                                                               \
                cp16(sB + ((st) * GST + r * HP) * 2 + ch * 16,                 \
                     W + (size_t)(n0 + r) * DMODEL + (k0) + ch * 8);           \
        }                                                                      \
    }

    G_ISSUE(0, 0);   cpcommit();
    G_ISSUE(1, 64);  cpcommit();
    G_ISSUE(2, 128); cpcommit();

    float acc[2][8][4];
#pragma unroll
    for (int t = 0; t < 2; t++)
#pragma unroll
        for (int j = 0; j < 8; j++)
#pragma unroll
            for (int c = 0; c < 4; c++) acc[t][j][c] = 0.f;

    int st = 0;
    for (int kt = 0; kt < 8; kt++) {
        cpwait<2>();               // oldest of 3 groups complete
        __syncthreads();
        const uint32_t Ab = sA + st * GST * 2;
        const uint32_t Bb = sB + st * GST * 2;
#pragma unroll
        for (int kc = 0; kc < 4; kc++) {
            uint32_t a[2][4];
#pragma unroll
            for (int t = 0; t < 2; t++) {
                const int row = wm + t * 16 + rA8 + lr;
                const int ko  = kc * 16 + kA8;
                ldsm4(a[t][0], a[t][1], a[t][2], a[t][3],
                      Ab + (row * HP + ko) * 2);
            }
#pragma unroll
            for (int jp = 0; jp < 4; jp++) {
                uint32_t b[4];
                const int row = wn + jp * 16 + rB8 + lr;
                const int ko  = kc * 16 + kB8;
                ldsm4(b[0], b[1], b[2], b[3], Bb + (row * HP + ko) * 2);
                mma_f16(acc[0][2 * jp    ], a[0], b[0], b[1]);
                mma_f16(acc[1][2 * jp    ], a[1], b[0], b[1]);
                mma_f16(acc[0][2 * jp + 1], a[0], b[2], b[3]);
                mma_f16(acc[1][2 * jp + 1], a[1], b[2], b[3]);
            }
        }
        __syncthreads();
        if (kt + 3 < 8) { G_ISSUE(st, (kt + 3) * 64); }
        cpcommit();
        st = (st == 2) ? 0 : st + 1;
    }

#pragma unroll
    for (int t = 0; t < 2; t++) {
#pragma unroll
        for (int rr = 0; rr < 2; rr++) {
            const int r = m0 + wm + t * 16 + g + rr * 8;
            const int bb = r >> 12, ss = r & 4095;
#pragma unroll
            for (int j = 0; j < 8; j++) {
                const int n = n0 + wn + j * 8 + 2 * tg;
                float2 bi = *(const float2*)&bias[n];
                float v0 = (acc[t][j][rr * 2 + 0] + bi.x) * scale;
                float v1 = (acc[t][j][rr * 2 + 1] + bi.y) * scale;
                if (LAYOUT == 0) {
                    *(float2*)&((float*)Yv)[(size_t)r * DMODEL + n]
                        = make_float2(v0, v1);
                } else if (LAYOUT == 1) {
                    const int h = n >> 6, d = n & 63;
                    *(__half2*)&((__half*)Yv)[
                        (((size_t)(bb * NHEAD + h)) * SEQ + ss) * DK + d]
                        = __floats2half2_rn(v0, v1);
                } else {
                    const int h = n >> 6, d = n & 63;
                    __half* yb = (__half*)Yv
                        + (((size_t)(bb * NHEAD + h)) * DK + d) * SEQ + ss;
                    yb[0]   = __float2half_rn(v0);
                    yb[SEQ] = __float2half_rn(v1);
                }
            }
        }
    }
#undef G_ISSUE
}

// Fused QKV projections: blockIdx.z selects input/weight/output.
__global__ __launch_bounds__(256, 2)
void gemm_qkv(const __half* __restrict__ rq, const __half* __restrict__ rk,
              const __half* __restrict__ rv, const __half* __restrict__ rw,
              const float* __restrict__ bq, const float* __restrict__ bk,
              const float* __restrict__ bv,
              __half* __restrict__ qh, __half* __restrict__ kh,
              __half* __restrict__ vh, float qscale)
{
    extern __shared__ __half smh[];
    const int m0 = blockIdx.y * 128, n0 = blockIdx.x * 128;
    const int DD = DMODEL * DMODEL;
    if (blockIdx.z == 0)
        gemm_body<1>(rq, rw,          bq, qh, qscale, m0, n0, smh);
    else if (blockIdx.z == 1)
        gemm_body<1>(rk, rw + DD,     bk, kh, 1.0f,   m0, n0, smh);
    else
        gemm_body<2>(rv, rw + 2 * DD, bv, vh, 1.0f,   m0, n0, smh);
}

// Output projection (fp32 result into d_out)
__global__ __launch_bounds__(256, 2)
void gemm_o(const __half* __restrict__ X, const __half* __restrict__ W,
            const float* __restrict__ bias, float* __restrict__ Y)
{
    extern __shared__ __half smh[];
    gemm_body<0>(X, W, bias, Y, 1.0f, blockIdx.y * 128, blockIdx.x * 128, smh);
}

// ---------------------------------------------------------------------------
// fp16 flash attention (EXACT R9/R14 best: 221us, at the mma.sync rate wall):
// 256 thr (8 warps) x 256 query rows, 32 rows/warp (2 m16 halves, K/V
// fragments shared). P entirely in registers. ldmatrix.x4 fragments.
// Softmax in exp2 domain (log2e folded into Q projection scale).
// ---------------------------------------------------------------------------
#define QROWS 256
#define KVB (64*HP)                       // halves per K or V stage
#define SM_K (QROWS*HP)                   // Q buffer first
#define SM_V (SM_K + 2*KVB)
#define ATT_SMEM ((SM_V + 2*KVB)*2)       // 73728 B

__global__ __launch_bounds__(256)
void attn_kernel()
{
    extern __shared__ __half smh[];

    const int bh = blockIdx.y, q0 = blockIdx.x * QROWS;
    const int tid = threadIdx.x, lane = tid & 31, warp = tid >> 5;
    const int w32 = warp * 32;
    const int lj = lane >> 3, lr = lane & 7;
    const int rA8 = (lj & 1) * 8, kA8 = (lj >> 1) * 8;
    const int rB8 = (lj >> 1) * 8, kB8 = (lj & 1) * 8;

    const __half* Qg = g_qh + (size_t)bh * SEQ * DK + (size_t)q0 * DK;
    const __half* Kg = g_kh + (size_t)bh * SEQ * DK;
    const __half* Vg = g_vh + (size_t)bh * DK * SEQ;

    const uint32_t sQ = (uint32_t)__cvta_generic_to_shared(smh);
    const uint32_t sK = sQ + SM_K * 2;
    const uint32_t sV = sQ + SM_V * 2;

    // Q tile: 256 rows x 8 chunks = 2048
#pragma unroll
    for (int i = 0; i < 8; i++) {
        int c = tid + i * 256;
        int row = c >> 3, ch = c & 7;
        cp16(sQ + row * (HP * 2) + ch * 16, Qg + (size_t)row * DK + ch * 8);
    }
    cpcommit();

#define KV_ISSUE(st, ktile)                                                    \
    {                                                                          \
        _Pragma("unroll")                                                      \
        for (int i = 0; i < 4; i++) {                                          \
            int c = tid + i * 256;                                             \
            int r = (c >> 3) & 63, ch = c & 7;                                 \
            if (c < 512)                                                       \
                cp16(sK + (st) * (KVB * 2) + r * (HP * 2) + ch * 16,           \
                     Kg + ((size_t)(ktile) * 64 + r) * DK + ch * 8);           \
            else                                                               \
                cp16(sV + (st) * (KVB * 2) + r * (HP * 2) + ch * 16,           \
                     Vg + (size_t)r * SEQ + (ktile) * 64 + ch * 8);            \
        }                                                                      \
    }

    KV_ISSUE(0, 0); cpcommit();
    KV_ISSUE(1, 1); cpcommit();

    cpwait<2>();
    __syncthreads();

    // Q fragments via ldmatrix: 2 halves x 4 k16 chunks
    uint32_t qa[2][4][4];
#pragma unroll
    for (int h = 0; h < 2; h++)
#pragma unroll
        for (int kc = 0; kc < 4; kc++) {
            const int row = w32 + h * 16 + rA8 + lr;
            const int ko  = kc * 16 + kA8;
            ldsm4(qa[h][kc][0], qa[h][kc][1], qa[h][kc][2], qa[h][kc][3],
                  sQ + (row * HP + ko) * 2);
        }

    float o[2][8][4];
    float m[2][2], l[2][2];
#pragma unroll
    for (int h = 0; h < 2; h++) {
        m[h][0] = -1e30f; m[h][1] = -1e30f; l[h][0] = 0.f; l[h][1] = 0.f;
#pragma unroll
        for (int nt = 0; nt < 8; nt++)
#pragma unroll
            for (int c = 0; c < 4; c++) o[h][nt][c] = 0.f;
    }

    for (int kt = 0; kt < SEQ / 64; kt++) {
        cpwait<1>();
        __syncthreads();
        const uint32_t kbase = sK + (kt & 1) * (KVB * 2);
        const uint32_t vbase = sV + (kt & 1) * (KVB * 2);

        // ---- S = Q @ K^T ----
        float sc[2][8][4];
#pragma unroll
        for (int h = 0; h < 2; h++)
#pragma unroll
            for (int nt = 0; nt < 8; nt++)
#pragma unroll
                for (int c = 0; c < 4; c++) sc[h][nt][c] = 0.f;

#pragma unroll
        for (int kc = 0; kc < 4; kc++) {
            uint32_t kb[4][4];
#pragma unroll
            for (int np = 0; np < 4; np++) {
                const int key = np * 16 + rB8 + lr;
                const int ko  = kc * 16 + kB8;
                ldsm4(kb[np][0], kb[np][1], kb[np][2], kb[np][3],
                      kbase + (key * HP + ko) * 2);
            }
#pragma unroll
            for (int np = 0; np < 4; np++) {
                mma_f16(sc[0][2 * np    ], qa[0][kc], kb[np][0], kb[np][1]);
                mma_f16(sc[1][2 * np    ], qa[1][kc], kb[np][0], kb[np][1]);
                mma_f16(sc[0][2 * np + 1], qa[0][kc], kb[np][2], kb[np][3]);
                mma_f16(sc[1][2 * np + 1], qa[1][kc], kb[np][2], kb[np][3]);
            }
        }

        // ---- Online softmax (exp2 domain); p overwrites sc ----
#pragma unroll
        for (int h = 0; h < 2; h++) {
            float mx0 = -1e30f, mx1 = -1e30f;
#pragma unroll
            for (int nt = 0; nt < 8; nt++) {
                mx0 = fmaxf(mx0, fmaxf(sc[h][nt][0], sc[h][nt][1]));
                mx1 = fmaxf(mx1, fmaxf(sc[h][nt][2], sc[h][nt][3]));
            }
            mx0 = fmaxf(mx0, __shfl_xor_sync(0xffffffffu, mx0, 1));
            mx0 = fmaxf(mx0, __shfl_xor_sync(0xffffffffu, mx0, 2));
            mx1 = fmaxf(mx1, __shfl_xor_sync(0xffffffffu, mx1, 1));
            mx1 = fmaxf(mx1, __shfl_xor_sync(0xffffffffu, mx1, 2));

            const float mn0 = fmaxf(m[h][0], mx0), mn1 = fmaxf(m[h][1], mx1);
            const float c0 = ex2(m[h][0] - mn0), c1 = ex2(m[h][1] - mn1);
            m[h][0] = mn0; m[h][1] = mn1;

            float s0 = 0.f, s1 = 0.f;
#pragma unroll
            for (int nt = 0; nt < 8; nt++) {
                sc[h][nt][0] = ex2(sc[h][nt][0] - mn0);
                sc[h][nt][1] = ex2(sc[h][nt][1] - mn0);
                sc[h][nt][2] = ex2(sc[h][nt][2] - mn1);
                sc[h][nt][3] = ex2(sc[h][nt][3] - mn1);
                s0 += sc[h][nt][0] + sc[h][nt][1];
                s1 += sc[h][nt][2] + sc[h][nt][3];
            }
            s0 += __shfl_xor_sync(0xffffffffu, s0, 1);
            s0 += __shfl_xor_sync(0xffffffffu, s0, 2);
            s1 += __shfl_xor_sync(0xffffffffu, s1, 1);
            s1 += __shfl_xor_sync(0xffffffffu, s1, 2);
            l[h][0] = l[h][0] * c0 + s0;
            l[h][1] = l[h][1] * c1 + s1;
#pragma unroll
            for (int nt = 0; nt < 8; nt++) {
                o[h][nt][0] *= c0; o[h][nt][1] *= c0;
                o[h][nt][2] *= c1; o[h][nt][3] *= c1;
            }
        }

        // ---- O += P @ V : P packed in registers (C-frag == A-frag) ----
#pragma unroll
        for (int kc = 0; kc < 4; kc++) {
            uint32_t vb[4][4];
#pragma unroll
            for (int np = 0; np < 4; np++) {
                const int d  = np * 16 + rB8 + lr;
                const int ko = kc * 16 + kB8;
                ldsm4(vb[np][0], vb[np][1], vb[np][2], vb[np][3],
                      vbase + (d * HP + ko) * 2);
            }
            const int n0b = 2 * kc, n1b = 2 * kc + 1;
            uint32_t pa0[4], pa1[4];
            pa0[0] = h2(sc[0][n0b][0], sc[0][n0b][1]);
            pa0[1] = h2(sc[0][n0b][2], sc[0][n0b][3]);
            pa0[2] = h2(sc[0][n1b][0], sc[0][n1b][1]);
            pa0[3] = h2(sc[0][n1b][2], sc[0][n1b][3]);
            pa1[0] = h2(sc[1][n0b][0], sc[1][n0b][1]);
            pa1[1] = h2(sc[1][n0b][2], sc[1][n0b][3]);
            pa1[2] = h2(sc[1][n1b][0], sc[1][n1b][1]);
            pa1[3] = h2(sc[1][n1b][2], sc[1][n1b][3]);
#pragma unroll
            for (int np = 0; np < 4; np++) {
                mma_f16(o[0][2 * np    ], pa0, vb[np][0], vb[np][1]);
                mma_f16(o[1][2 * np    ], pa1, vb[np][0], vb[np][1]);
                mma_f16(o[0][2 * np + 1], pa0, vb[np][2], vb[np][3]);
                mma_f16(o[1][2 * np + 1], pa1, vb[np][2], vb[np][3]);
            }
        }
        __syncthreads();   // all warps done with stage before refill
        if (kt + 2 < SEQ / 64) { KV_ISSUE(kt & 1, kt + 2); }
        cpcommit();
    }

    // Epilogue: normalize, write fp16 [B,S,D] (feeds fp16 O-GEMM)
    const int g = lane >> 2, tg = lane & 3;
    const int bb = bh >> 3, hh = bh & 7;
    __half* Og = g_att + ((size_t)bb * SEQ + q0) * DMODEL + hh * DK;
#pragma unroll
    for (int h = 0; h < 2; h++) {
#pragma unroll
        for (int rr = 0; rr < 2; rr++) {
            const float inv = 1.0f / l[h][rr];
            const int row = w32 + h * 16 + g + rr * 8;
#pragma unroll
            for (int nt = 0; nt < 8; nt++) {
                *(__half2*)&Og[(size_t)row * DMODEL + nt * 8 + 2 * tg]
                    = __floats2half2_rn(o[h][nt][rr * 2 + 0] * inv,
                                        o[h][nt][rr * 2 + 1] * inv);
            }
        }
    }
#undef KV_ISSUE
}

// ---------------------------------------------------------------------------
extern "C" void kernel_launch(void* const* d_in, const int* in_sizes, int n_in,
                              void* d_out, int out_size)
{
    const float* q  = (const float*)d_in[0];
    const float* k  = (const float*)d_in[1];
    const float* v  = (const float*)d_in[2];
    const float* wq = (const float*)d_in[3];
    const float* bq = (const float*)d_in[4];
    const float* wk = (const float*)d_in[5];
    const float* bk = (const float*)d_in[6];
    const float* wv = (const float*)d_in[7];
    const float* bv = (const float*)d_in[8];
    const float* wo = (const float*)d_in[9];
    const float* bo = (const float*)d_in[10];

    __half *qh, *kh, *vh, *att, *rq, *rk, *rv, *rw;
    cudaGetSymbolAddress((void**)&qh,  g_qh);
    cudaGetSymbolAddress((void**)&kh,  g_kh);
    cudaGetSymbolAddress((void**)&vh,  g_vh);
    cudaGetSymbolAddress((void**)&att, g_att);
    cudaGetSymbolAddress((void**)&rq,  g_rq);
    cudaGetSymbolAddress((void**)&rk,  g_rk);
    cudaGetSymbolAddress((void**)&rv,  g_rv);
    cudaGetSymbolAddress((void**)&rw,  g_rw);

    cudaFuncSetAttribute(gemm_qkv,
        cudaFuncAttributeMaxDynamicSharedMemorySize, GEMM_SMEM);
    cudaFuncSetAttribute(gemm_o,
        cudaFuncAttributeMaxDynamicSharedMemorySize, GEMM_SMEM);
    cudaFuncSetAttribute(attn_kernel,
        cudaFuncAttributeMaxDynamicSharedMemorySize, ATT_SMEM);

    const int DD = DMODEL * DMODEL;
    const int n4x = MTOT * DMODEL / 4;   // 1048576
    const int n4w = DD / 4;              // 65536

    conv_all<<<dim3(256, 7), 256>>>((const float4*)q, (const float4*)k,
                                    (const float4*)v, (const float4*)wq,
                                    (const float4*)wk, (const float4*)wv,
                                    (const float4*)wo, (__half2*)rq,
                                    (__half2*)rk, (__half2*)rv,
                                    (__half2*)rw, n4x, n4w);

    const float QSCALE = 0.125f * 1.4426950408889634f;   // 1/sqrt(Dk) * log2e
    gemm_qkv<<<dim3(DMODEL / 128, MTOT / 128, 3), 256, GEMM_SMEM>>>(
        rq, rk, rv, rw, bq, bk, bv, qh, kh, vh, QSCALE);

    attn_kernel<<<dim3(SEQ / QROWS, BATCH * NHEAD), 256, ATT_SMEM>>>();

    gemm_o<<<dim3(DMODEL / 128, MTOT / 128), 256, GEMM_SMEM>>>(
        att, rw + 3 * DD, bo, (float*)d_out);
}